// round 3
// baseline (speedup 1.0000x reference)
#include <cuda_runtime.h>

#define NN 100000
#define EE 3200000
#define GG 1024

// ---- scratch (allocation-free: __device__ globals) ----
__device__ int   d_is64;                 // 1 if index inputs are int64
__device__ __align__(16) float d_deg[NN];
__device__ float d_dinv[NN];
__device__ __align__(16) int   d_row[EE];
__device__ __align__(16) int   d_col[EE];
__device__ __align__(16) float d_g1[NN * 16];
__device__ __align__(16) float d_acc1[NN * 16];
__device__ __align__(16) float d_g2[NN * 8];
__device__ __align__(16) float d_acc2[NN * 8];
__device__ __align__(16) float d_sums[GG * 8];
__device__ float d_cnt[GG];

// init: deg=1 (self loop), pooled sums/cnt = 0, and dtype detection.
// If int64: high 32-bit words of the first 64 entries are all zero (indices < 1e5).
// If int32: those words are random row indices — essentially never all zero.
__global__ void k_init(const int* __restrict__ ei32) {
    int i = blockIdx.x * blockDim.x + threadIdx.x;
    if (i < NN) d_deg[i] = 1.0f;
    if (i < GG * 8) d_sums[i] = 0.0f;
    if (i < GG) d_cnt[i] = 0.0f;
    if (i == 0) {
        int all0 = 1;
        for (int k = 0; k < 64; k++)
            if (ei32[2 * k + 1] != 0) { all0 = 0; break; }
        d_is64 = all0;
    }
}

// prep: convert edge indices to int32 scratch + degree count over col
__global__ void __launch_bounds__(256) k_prep(const void* __restrict__ ei, int E) {
    int e = blockIdx.x * blockDim.x + threadIdx.x;
    if (e >= E) return;
    int r, c;
    if (d_is64) {
        const long long* p = (const long long*)ei;
        r = (int)p[e];
        c = (int)p[E + e];
    } else {
        const int* p = (const int*)ei;
        r = p[e];
        c = p[E + e];
    }
    d_row[e] = r;
    d_col[e] = c;
    atomicAdd(&d_deg[c], 1.0f);
}

// node prologue: dinv, h0 = [x0*W_emb^T + b_emb, xyz], g1 = (h0 @ W1^T) * dinv
// acc1 initialized to g1 (self-loop contribution)
__global__ void k_node0(const float* __restrict__ x,
                        const float* __restrict__ W_emb,
                        const float* __restrict__ b_emb,
                        const float* __restrict__ W1) {
    int i = blockIdx.x * blockDim.x + threadIdx.x;
    if (i >= NN) return;
    float dinv = rsqrtf(d_deg[i]);   // deg >= 1 always (self loop)
    d_dinv[i] = dinv;
    float4 xi = reinterpret_cast<const float4*>(x)[i];
    float h[7];
    h[0] = xi.x * W_emb[0] + b_emb[0];
    h[1] = xi.x * W_emb[1] + b_emb[1];
    h[2] = xi.x * W_emb[2] + b_emb[2];
    h[3] = xi.x * W_emb[3] + b_emb[3];
    h[4] = xi.y; h[5] = xi.z; h[6] = xi.w;
#pragma unroll
    for (int k = 0; k < 16; k++) {
        float s = 0.0f;
#pragma unroll
        for (int j = 0; j < 7; j++) s = fmaf(W1[k * 7 + j], h[j], s);
        float g = s * dinv;
        d_g1[i * 16 + k] = g;
        d_acc1[i * 16 + k] = g;
    }
}

// edge scatter layer 1: acc1[col] += g1[row]  (16 floats = 4x red.v4)
__global__ void __launch_bounds__(256) k_edge1(int E) {
    int e = blockIdx.x * blockDim.x + threadIdx.x;
    if (e >= E) return;
    int r = d_row[e];
    int c = d_col[e];
    const float4* src = reinterpret_cast<const float4*>(&d_g1[r * 16]);
    float4* dst = reinterpret_cast<float4*>(&d_acc1[c * 16]);
#pragma unroll
    for (int q = 0; q < 4; q++) {
        float4 v = src[q];
        asm volatile("red.global.add.v4.f32 [%0], {%1,%2,%3,%4};"
                     :: "l"(dst + q), "f"(v.x), "f"(v.y), "f"(v.z), "f"(v.w)
                     : "memory");
    }
}

// node mid: h1 = tanh(dinv*acc1 + b1); g2 = (h1 @ W2^T) * dinv; acc2 = g2
__global__ void k_node1(const float* __restrict__ W2, const float* __restrict__ b1) {
    int i = blockIdx.x * blockDim.x + threadIdx.x;
    if (i >= NN) return;
    float dinv = d_dinv[i];
    float h[16];
#pragma unroll
    for (int k = 0; k < 16; k++)
        h[k] = tanhf(fmaf(dinv, d_acc1[i * 16 + k], b1[k]));
#pragma unroll
    for (int k = 0; k < 8; k++) {
        float s = 0.0f;
#pragma unroll
        for (int j = 0; j < 16; j++) s = fmaf(W2[k * 16 + j], h[j], s);
        float g = s * dinv;
        d_g2[i * 8 + k] = g;
        d_acc2[i * 8 + k] = g;
    }
}

// edge scatter layer 2: acc2[col] += g2[row]  (8 floats = 2x red.v4)
__global__ void __launch_bounds__(256) k_edge2(int E) {
    int e = blockIdx.x * blockDim.x + threadIdx.x;
    if (e >= E) return;
    int r = d_row[e];
    int c = d_col[e];
    const float4* src = reinterpret_cast<const float4*>(&d_g2[r * 8]);
    float4* dst = reinterpret_cast<float4*>(&d_acc2[c * 8]);
#pragma unroll
    for (int q = 0; q < 2; q++) {
        float4 v = src[q];
        asm volatile("red.global.add.v4.f32 [%0], {%1,%2,%3,%4};"
                     :: "l"(dst + q), "f"(v.x), "f"(v.y), "f"(v.z), "f"(v.w)
                     : "memory");
    }
}

// node epilogue: h2 = tanh(dinv*acc2 + b2); pool into d_sums/d_cnt by batch
__global__ void k_node2(const void* __restrict__ batch, const float* __restrict__ b2) {
    int i = blockIdx.x * blockDim.x + threadIdx.x;
    if (i >= NN) return;
    float dinv = d_dinv[i];
    int b = d_is64 ? (int)((const long long*)batch)[i] : ((const int*)batch)[i];
#pragma unroll
    for (int k = 0; k < 8; k++) {
        float h = tanhf(fmaf(dinv, d_acc2[i * 8 + k], b2[k]));
        atomicAdd(&d_sums[b * 8 + k], h);
    }
    atomicAdd(&d_cnt[b], 1.0f);
}

// final: out[g] = (sums/max(cnt,1)) . W3 + b3
__global__ void k_final(const float* __restrict__ W3, const float* __restrict__ b3,
                        float* __restrict__ out) {
    int g = blockIdx.x * blockDim.x + threadIdx.x;
    if (g >= GG) return;
    float c = fmaxf(d_cnt[g], 1.0f);
    float s = 0.0f;
#pragma unroll
    for (int k = 0; k < 8; k++) s = fmaf(d_sums[g * 8 + k], W3[k], s);
    out[g] = s / c + b3[0];
}

extern "C" void kernel_launch(void* const* d_in, const int* in_sizes, int n_in,
                              void* d_out, int out_size) {
    const float* x     = (const float*)d_in[0];
    const void*  ei    = d_in[1];
    const void*  batch = d_in[2];
    const float* W_emb = (const float*)d_in[3];
    const float* b_emb = (const float*)d_in[4];
    const float* W1    = (const float*)d_in[5];
    const float* b1    = (const float*)d_in[6];
    const float* W2    = (const float*)d_in[7];
    const float* b2    = (const float*)d_in[8];
    const float* W3    = (const float*)d_in[9];
    const float* b3    = (const float*)d_in[10];
    float* out = (float*)d_out;

    int E = in_sizes[1] / 2;
    if (E > EE) E = EE;

    int nb = (NN + 255) / 256;
    int eb = (E + 255) / 256;

    k_init<<<nb, 256>>>((const int*)ei);
    k_prep<<<eb, 256>>>(ei, E);
    k_node0<<<nb, 256>>>(x, W_emb, b_emb, W1);
    k_edge1<<<eb, 256>>>(E);
    k_node1<<<nb, 256>>>(W2, b1);
    k_edge2<<<eb, 256>>>(E);
    k_node2<<<nb, 256>>>(batch, b2);
    k_final<<<(GG + 255) / 256, 256>>>(W3, b3, out);
}

// round 5
// speedup vs baseline: 1.2856x; 1.2856x over previous
#include <cuda_runtime.h>

#define NN 100000
#define EE 3200000
#define GG 1024

// ---- scratch (allocation-free: __device__ globals) ----
__device__ int   d_is64;                 // 1 if index inputs are int64
__device__ __align__(16) float d_deg[NN];
__device__ float d_dinv[NN];
__device__ __align__(16) int2  d_rc[EE];           // interleaved (row,col)
__device__ __align__(32) float d_p[NN * 8];        // per-node 5-float message (padded to 8)
__device__ __align__(32) float d_s[NN * 8];        // aggregated 5-float sums (padded to 8)
__device__ __align__(16) float d_g2[NN * 8];
__device__ __align__(16) float d_acc2[NN * 8];
__device__ __align__(16) float d_sums[GG * 8];
__device__ float d_cnt[GG];

// init: deg=1 (self loop), pooled sums/cnt = 0, and dtype detection.
// int64 indices < 1e5 have all-zero high words; int32 data there is random.
__global__ void k_init(const int* __restrict__ ei32) {
    int i = blockIdx.x * blockDim.x + threadIdx.x;
    if (i < NN) d_deg[i] = 1.0f;
    if (i < GG * 8) d_sums[i] = 0.0f;
    if (i < GG) d_cnt[i] = 0.0f;
    if (i == 0) {
        int all0 = 1;
        for (int k = 0; k < 64; k++)
            if (ei32[2 * k + 1] != 0) { all0 = 0; break; }
        d_is64 = all0;
    }
}

// prep: convert edge indices to interleaved int2 + degree count over col
__global__ void __launch_bounds__(256) k_prep(const void* __restrict__ ei, int E) {
    int e = blockIdx.x * blockDim.x + threadIdx.x;
    if (e >= E) return;
    int r, c;
    if (d_is64) {
        const long long* p = (const long long*)ei;
        r = (int)p[e];
        c = (int)p[E + e];
    } else {
        const int* p = (const int*)ei;
        r = p[e];
        c = p[E + e];
    }
    d_rc[e] = make_int2(r, c);
    atomicAdd(&d_deg[c], 1.0f);
}

// node prologue: dinv; p[i] = (dinv*x0, dinv*x, dinv*y, dinv*z | dinv);
// s[i] initialized to p[i] (self-loop contribution folded in).
__global__ void k_node0(const float* __restrict__ x) {
    int i = blockIdx.x * blockDim.x + threadIdx.x;
    if (i >= NN) return;
    float dinv = rsqrtf(d_deg[i]);   // deg >= 1 always (self loop)
    d_dinv[i] = dinv;
    float4 xi = reinterpret_cast<const float4*>(x)[i];
    float4 p4 = make_float4(dinv * xi.x, dinv * xi.y, dinv * xi.z, dinv * xi.w);
    reinterpret_cast<float4*>(&d_p[i * 8])[0] = p4;
    d_p[i * 8 + 4] = dinv;
    reinterpret_cast<float4*>(&d_s[i * 8])[0] = p4;
    d_s[i * 8 + 4] = dinv;
}

// edge scatter layer 1: s[col] += p[row]   (5 floats: red.v4 + red.f32)
__global__ void __launch_bounds__(256) k_edge1(int E) {
    int e = blockIdx.x * blockDim.x + threadIdx.x;
    if (e >= E) return;
    int2 rc = d_rc[e];
    const float* src = &d_p[rc.x * 8];
    float* dst = &d_s[rc.y * 8];
    float4 v = reinterpret_cast<const float4*>(src)[0];
    float  w = src[4];
    asm volatile("red.global.add.v4.f32 [%0], {%1,%2,%3,%4};"
                 :: "l"(dst), "f"(v.x), "f"(v.y), "f"(v.z), "f"(v.w) : "memory");
    asm volatile("red.global.add.f32 [%0], %1;"
                 :: "l"(dst + 4), "f"(w) : "memory");
}

// node mid: reconstruct 7-dim aggregate from (S4,S1), apply W1+b1, tanh,
// then g2 = (h1 @ W2^T) * dinv; acc2 initialized to g2 (self loop).
__global__ void k_node1(const float* __restrict__ W_emb,
                        const float* __restrict__ b_emb,
                        const float* __restrict__ W1,
                        const float* __restrict__ b1,
                        const float* __restrict__ W2) {
    int i = blockIdx.x * blockDim.x + threadIdx.x;
    if (i >= NN) return;
    float dinv = d_dinv[i];
    float4 S4 = reinterpret_cast<const float4*>(&d_s[i * 8])[0];
    float  S1 = d_s[i * 8 + 4];
    // agg7 = dinv * (M*S4 + k*S1):  h0 = [x0*W_emb^T + b_emb, xyz]
    float a[7];
#pragma unroll
    for (int j = 0; j < 4; j++)
        a[j] = dinv * fmaf(W_emb[j], S4.x, b_emb[j] * S1);
    a[4] = dinv * S4.y;
    a[5] = dinv * S4.z;
    a[6] = dinv * S4.w;
    float h[16];
#pragma unroll
    for (int k = 0; k < 16; k++) {
        float s = b1[k];
#pragma unroll
        for (int j = 0; j < 7; j++) s = fmaf(W1[k * 7 + j], a[j], s);
        h[k] = tanhf(s);
    }
#pragma unroll
    for (int m = 0; m < 8; m++) {
        float s = 0.0f;
#pragma unroll
        for (int k = 0; k < 16; k++) s = fmaf(W2[m * 16 + k], h[k], s);
        float g = s * dinv;
        d_g2[i * 8 + m] = g;
        d_acc2[i * 8 + m] = g;
    }
}

// edge scatter layer 2: acc2[col] += g2[row]  (8 floats = 2x red.v4)
__global__ void __launch_bounds__(256) k_edge2(int E) {
    int e = blockIdx.x * blockDim.x + threadIdx.x;
    if (e >= E) return;
    int2 rc = d_rc[e];
    const float4* src = reinterpret_cast<const float4*>(&d_g2[rc.x * 8]);
    float4* dst = reinterpret_cast<float4*>(&d_acc2[rc.y * 8]);
#pragma unroll
    for (int q = 0; q < 2; q++) {
        float4 v = src[q];
        asm volatile("red.global.add.v4.f32 [%0], {%1,%2,%3,%4};"
                     :: "l"(dst + q), "f"(v.x), "f"(v.y), "f"(v.z), "f"(v.w)
                     : "memory");
    }
}

// node epilogue: h2 = tanh(dinv*acc2 + b2); pool into d_sums/d_cnt by batch
__global__ void k_node2(const void* __restrict__ batch, const float* __restrict__ b2) {
    int i = blockIdx.x * blockDim.x + threadIdx.x;
    if (i >= NN) return;
    float dinv = d_dinv[i];
    int b = d_is64 ? (int)((const long long*)batch)[i] : ((const int*)batch)[i];
#pragma unroll
    for (int k = 0; k < 8; k++) {
        float h = tanhf(fmaf(dinv, d_acc2[i * 8 + k], b2[k]));
        atomicAdd(&d_sums[b * 8 + k], h);
    }
    atomicAdd(&d_cnt[b], 1.0f);
}

// final: out[g] = (sums/max(cnt,1)) . W3 + b3
__global__ void k_final(const float* __restrict__ W3, const float* __restrict__ b3,
                        float* __restrict__ out) {
    int g = blockIdx.x * blockDim.x + threadIdx.x;
    if (g >= GG) return;
    float c = fmaxf(d_cnt[g], 1.0f);
    float s = 0.0f;
#pragma unroll
    for (int k = 0; k < 8; k++) s = fmaf(d_sums[g * 8 + k], W3[k], s);
    out[g] = s / c + b3[0];
}

extern "C" void kernel_launch(void* const* d_in, const int* in_sizes, int n_in,
                              void* d_out, int out_size) {
    const float* x     = (const float*)d_in[0];
    const void*  ei    = d_in[1];
    const void*  batch = d_in[2];
    const float* W_emb = (const float*)d_in[3];
    const float* b_emb = (const float*)d_in[4];
    const float* W1    = (const float*)d_in[5];
    const float* b1    = (const float*)d_in[6];
    const float* W2    = (const float*)d_in[7];
    const float* b2    = (const float*)d_in[8];
    const float* W3    = (const float*)d_in[9];
    const float* b3    = (const float*)d_in[10];
    float* out = (float*)d_out;

    int E = in_sizes[1] / 2;
    if (E > EE) E = EE;

    int nb = (NN + 255) / 256;
    int eb = (E + 255) / 256;

    k_init<<<nb, 256>>>((const int*)ei);
    k_prep<<<eb, 256>>>(ei, E);
    k_node0<<<nb, 256>>>(x);
    k_edge1<<<eb, 256>>>(E);
    k_node1<<<nb, 256>>>(W_emb, b_emb, W1, b1, W2);
    k_edge2<<<eb, 256>>>(E);
    k_node2<<<nb, 256>>>(batch, b2);
    k_final<<<(GG + 255) / 256, 256>>>(W3, b3, out);
}